// round 11
// baseline (speedup 1.0000x reference)
#include <cuda_runtime.h>

#define NB 16
#define NS 4096
#define NTOK (NB*NS)
#define CHUNK 256
#define KS 264             // padded f32 stride for K rows
#define VS 132             // padded u32 stride for V rows (bf16x2)
#define NCH (NS/CHUNK)

// scratch (device globals: no allocation allowed)
__device__ float g_qrow[NTOK*8];            // tf32(q*log2e/sqrt2) [b][s][w] (Q operand)
__device__ float g_qcol[NB*8*NS];           // tf32(q)             [b][w][t] (K operand)
__device__ unsigned short g_vhi[NB*8*NS];   // bf16(q)             [b][w][t] (V operand)

typedef unsigned int u32;
typedef unsigned long long u64;

__device__ __forceinline__ float ex2f(float x){float r; asm("ex2.approx.ftz.f32 %0,%1;":"=f"(r):"f"(x)); return r;}
__device__ __forceinline__ float tf32r(float x){u32 r; asm("cvt.rna.tf32.f32 %0,%1;":"=r"(r):"f"(x)); return __uint_as_float(r);}
// pack: result.lo = lo, result.hi = hi
__device__ __forceinline__ u32 pkbf(float hi, float lo){u32 r; asm("cvt.rn.bf16x2.f32 %0,%1,%2;":"=r"(r):"f"(hi),"f"(lo)); return r;}
__device__ __forceinline__ u64 pk2(float lo, float hi){u64 r; asm("mov.b64 %0,{%1,%2};":"=l"(r):"f"(lo),"f"(hi)); return r;}
__device__ __forceinline__ float2 upk2(u64 v){float2 f; asm("mov.b64 {%0,%1},%2;":"=f"(f.x),"=f"(f.y):"l"(v)); return f;}
__device__ __forceinline__ u64 fma2(u64 a,u64 b,u64 c){u64 d; asm("fma.rn.f32x2 %0,%1,%2,%3;":"=l"(d):"l"(a),"l"(b),"l"(c)); return d;}
__device__ __forceinline__ u64 mul2(u64 a,u64 b){u64 d; asm("mul.rn.f32x2 %0,%1,%2;":"=l"(d):"l"(a),"l"(b)); return d;}
__device__ __forceinline__ void cpa16(u32 dst, const void* src){
    asm volatile("cp.async.cg.shared.global [%0], [%1], 16;"::"r"(dst),"l"(src));
}
__device__ __forceinline__ void cpa_commit(){ asm volatile("cp.async.commit_group;"); }
__device__ __forceinline__ void cpa_wait1(){ asm volatile("cp.async.wait_group 1;"); }

__device__ __forceinline__ void mma_tf32(float* d, const u32* a, u32 b0, u32 b1){
    asm volatile("mma.sync.aligned.m16n8k8.row.col.f32.tf32.tf32.f32 "
        "{%0,%1,%2,%3},{%4,%5,%6,%7},{%8,%9},{%10,%11,%12,%13};"
        : "=f"(d[0]),"=f"(d[1]),"=f"(d[2]),"=f"(d[3])
        : "r"(a[0]),"r"(a[1]),"r"(a[2]),"r"(a[3]), "r"(b0),"r"(b1),
          "f"(0.f),"f"(0.f),"f"(0.f),"f"(0.f));
}
__device__ __forceinline__ void mma_bf16(float* d, const u32* a, u32 b0, u32 b1){
    asm volatile("mma.sync.aligned.m16n8k16.row.col.f32.bf16.bf16.f32 "
        "{%0,%1,%2,%3},{%4,%5,%6,%7},{%8,%9},{%0,%1,%2,%3};"
        : "+f"(d[0]),"+f"(d[1]),"+f"(d[2]),"+f"(d[3])
        : "r"(a[0]),"r"(a[1]),"r"(a[2]),"r"(a[3]), "r"(b0),"r"(b1));
}

// ---------------------------------------------------------------------------
// Kernel 1: quantum features (prefix cosine products).
//   Emits: Q (tf32, pre-scaled), K (tf32), V (bf16).
// ---------------------------------------------------------------------------
__global__ void feat_kernel(const float* __restrict__ x, const float* __restrict__ theta)
{
    int tok = blockIdx.x*blockDim.x + threadIdx.x;
    float th[8];
    #pragma unroll
    for(int w=0;w<8;w++) th[w] = __ldg(&theta[w]);
    float4 x0 = *(const float4*)&x[tok*8];
    float4 x1 = *(const float4*)&x[tok*8+4];
    float c[8];
    c[0]=__cosf(x0.x+th[0]); c[1]=__cosf(x0.y+th[1]); c[2]=__cosf(x0.z+th[2]); c[3]=__cosf(x0.w+th[3]);
    c[4]=__cosf(x1.x+th[4]); c[5]=__cosf(x1.y+th[5]); c[6]=__cosf(x1.z+th[6]); c[7]=__cosf(x1.w+th[7]);
    float q[8];
    float p = c[0];
    #pragma unroll
    for(int w=1;w<8;w++){ p *= c[w]; q[w] = p; }
    float s = c[1];
    #pragma unroll
    for(int w=2;w<8;w++) s *= c[w];
    q[0] = s;                                   // CNOT-ring inverse image
    const float SC = 1.02013946f;               // log2(e)/sqrt(2)
    float qs[8];
    #pragma unroll
    for(int w=0;w<8;w++) qs[w]=tf32r(q[w]*SC);
    *(float4*)&g_qrow[tok*8]   = make_float4(qs[0],qs[1],qs[2],qs[3]);
    *(float4*)&g_qrow[tok*8+4] = make_float4(qs[4],qs[5],qs[6],qs[7]);
    int b = tok >> 12, t = tok & (NS-1);
    #pragma unroll
    for(int w=0;w<8;w++){
        float qv = q[w];
        g_qcol[(b*8+w)*NS + t] = tf32r(qv);
        g_vhi[(b*8+w)*NS + t] = (unsigned short)(pkbf(0.f, qv) & 0xffffu);
    }
}

// ---------------------------------------------------------------------------
// Kernel 2: flash attention via warp mma.sync + fused epilogue.
//   Two independent 16-t pipelines per iteration. Per subtile:
//     2x tf32 mma -> S ; 6x ex2 (MUFU) + 2 exps via packed f32x2 poly (FMA);
//     4x cvt -> P bf16 ; num-mma + den-mma (ones B-fragment).
//   MUFU floor drops 64 -> 48 cyc/subtile; den FADDs + end shuffles removed.
// ---------------------------------------------------------------------------
__global__ void __launch_bounds__(128, 7) attn_kernel(const float* __restrict__ W,
                                                      const float* __restrict__ bias,
                                                      float* __restrict__ out)
{
    __shared__ __align__(16) float sk[2][8*KS];
    __shared__ __align__(16) u32   svh[2][8*VS];
    __shared__ float so[64*9];                   // o staging, stride 9

    const int b    = blockIdx.y;
    const int tid  = threadIdx.x;
    const int warp = tid >> 5, lane = tid & 31;
    const int g    = lane >> 2, c = lane & 3;
    const int row0 = blockIdx.x*64 + warp*16;

    // hoisted chunk-load addressing
    const int kr = tid >> 6, ko = tid & 63;
    const int vr = tid >> 5, vo = tid & 31;
    const float*          ksrc = &g_qcol[b*8*NS + kr*NS] + ko*4;
    const unsigned short* vsrc = &g_vhi [b*8*NS + vr*NS] + vo*8;
    u32 skb  = (u32)__cvta_generic_to_shared(&sk[0][0])  + (u32)(kr*KS + ko*4)*4u;
    u32 svhb = (u32)__cvta_generic_to_shared(&svh[0][0]) + (u32)(vr*VS + vo*4)*4u;
    const u32 KSTG = 8*KS*4u, VSTG = 8*VS*4u;

    // Q fragment (held whole kernel)
    const float* qr = &g_qrow[(b*NS+row0)*8];
    u32 qa[4];
    qa[0] = __float_as_uint(qr[ g   *8 + c  ]);
    qa[1] = __float_as_uint(qr[(g+8)*8 + c  ]);
    qa[2] = __float_as_uint(qr[ g   *8 + c+4]);
    qa[3] = __float_as_uint(qr[(g+8)*8 + c+4]);

    float num0[4] = {0.f,0.f,0.f,0.f};
    float num1[4] = {0.f,0.f,0.f,0.f};
    float dden[4] = {0.f,0.f,0.f,0.f};
    const u32 ONEB = 0x3F803F80u;                // bf16x2 {1,1}

    // packed poly: exp2(v) = (exp(v*ln2/8))^8, |v*ln2/8| <= 0.71
    const u64 KK = pk2(0.08664339757f, 0.08664339757f);   // ln2/8
    const u64 C5 = pk2(8.4960e-3f, 8.4960e-3f);           // minimax-adj 1/120
    const u64 C4 = pk2(4.1666667e-2f, 4.1666667e-2f);
    const u64 C3 = pk2(0.16666667f, 0.16666667f);
    const u64 C2 = pk2(0.5f, 0.5f);
    const u64 ONE2 = pk2(1.f, 1.f);

    auto load_chunk = [&](int ch, int st){
        const float*          ks = ksrc + ch*CHUNK;
        const unsigned short* vs = vsrc + ch*CHUNK;
        u32 kb = skb  + (st ? KSTG : 0u);
        u32 hb = svhb + (st ? VSTG : 0u);
        #pragma unroll
        for(int k=0;k<4;k++) cpa16(kb + (u32)(2*k*KS)*4u, ks + 2*k*NS);
        #pragma unroll
        for(int k=0;k<2;k++) cpa16(hb + (u32)(4*k*VS)*4u, vs + 4*k*NS);
        cpa_commit();
    };

    load_chunk(0, 0);

    for(int ch=0; ch<NCH; ch++){
        int st = ch & 1;
        if(ch+1 < NCH) load_chunk(ch+1, (ch+1)&1);
        else           cpa_commit();           // keep wait count uniform
        cpa_wait1();
        __syncthreads();

        const float* K  = &sk[st][0];
        const u32*   VH = &svh[st][0];

        #pragma unroll 2
        for(int pair=0; pair<CHUNK/32; pair++){
            const int tA = pair*32, tB = pair*32 + 16;
            u32 a00 = __float_as_uint(K[ c   *KS + tA + g    ]);
            u32 a01 = __float_as_uint(K[(c+4)*KS + tA + g    ]);
            u32 a10 = __float_as_uint(K[ c   *KS + tA + 8 + g]);
            u32 a11 = __float_as_uint(K[(c+4)*KS + tA + 8 + g]);
            u32 b00 = __float_as_uint(K[ c   *KS + tB + g    ]);
            u32 b01 = __float_as_uint(K[(c+4)*KS + tB + g    ]);
            u32 b10 = __float_as_uint(K[ c   *KS + tB + 8 + g]);
            u32 b11 = __float_as_uint(K[(c+4)*KS + tB + 8 + g]);

            float Al[4], Ar[4], Bl[4], Br[4];
            mma_tf32(Al, qa, a00, a01);
            mma_tf32(Ar, qa, a10, a11);
            mma_tf32(Bl, qa, b00, b01);
            mma_tf32(Br, qa, b10, b11);

            // packed poly chains for Ar[2],Ar[3] and Br[2],Br[3] (FMA pipe)
            u64 uA = mul2(pk2(Ar[2],Ar[3]), KK);
            u64 uB = mul2(pk2(Br[2],Br[3]), KK);
            u64 pA4 = fma2(uA,C5,C4);
            u64 pB4 = fma2(uB,C5,C4);
            pA4 = fma2(pA4,uA,C3);  pB4 = fma2(pB4,uB,C3);
            pA4 = fma2(pA4,uA,C2);  pB4 = fma2(pB4,uB,C2);
            pA4 = fma2(pA4,uA,ONE2); pB4 = fma2(pB4,uB,ONE2);
            pA4 = fma2(pA4,uA,ONE2); pB4 = fma2(pB4,uB,ONE2);
            pA4 = mul2(pA4,pA4); pB4 = mul2(pB4,pB4);
            pA4 = mul2(pA4,pA4); pB4 = mul2(pB4,pB4);
            pA4 = mul2(pA4,pA4); pB4 = mul2(pB4,pB4);      // ^8

            // remaining 12 exps on MUFU
            Al[0]=ex2f(Al[0]); Al[1]=ex2f(Al[1]); Al[2]=ex2f(Al[2]); Al[3]=ex2f(Al[3]);
            Ar[0]=ex2f(Ar[0]); Ar[1]=ex2f(Ar[1]);
            Bl[0]=ex2f(Bl[0]); Bl[1]=ex2f(Bl[1]); Bl[2]=ex2f(Bl[2]); Bl[3]=ex2f(Bl[3]);
            Br[0]=ex2f(Br[0]); Br[1]=ex2f(Br[1]);

            float2 fA = upk2(pA4), fB = upk2(pB4);
            u32 pA[4], pB[4];
            pA[0]=pkbf(Al[1],Al[0]); pA[1]=pkbf(Al[3],Al[2]);
            pA[2]=pkbf(Ar[1],Ar[0]); pA[3]=pkbf(fA.y,fA.x);
            pB[0]=pkbf(Bl[1],Bl[0]); pB[1]=pkbf(Bl[3],Bl[2]);
            pB[2]=pkbf(Br[1],Br[0]); pB[3]=pkbf(fB.y,fB.x);

            int viA = g*VS + (tA>>1);
            int viB = g*VS + (tB>>1);
            mma_bf16(num0, pA, VH[viA + c], VH[viA + 4 + c]);
            mma_bf16(num1, pB, VH[viB + c], VH[viB + 4 + c]);
            mma_bf16(dden, pA, ONEB, ONEB);     // row sums -> den
            mma_bf16(dden, pB, ONEB, ONEB);
        }
        __syncthreads();
    }

    float invl = 1.0f/dden[0], invh = 1.0f/dden[2];

    // stage normalized o tile: so[localRow][e], stride 9
    int lr = warp*16 + g;
    so[ lr   *9 + 2*c] = (num0[0]+num1[0])*invl;  so[ lr   *9 + 2*c+1] = (num0[1]+num1[1])*invl;
    so[(lr+8)*9 + 2*c] = (num0[2]+num1[2])*invh;  so[(lr+8)*9 + 2*c+1] = (num0[3]+num1[3])*invh;
    __syncthreads();

    // fused epilogue: out[b, e*512 + 8*bx + m, :] = bias + so[8m+j][e] . W[:,j]
    if(tid < 64){
        int e = tid >> 3, m = tid & 7;
        float y[8];
        #pragma unroll
        for(int j=0;j<8;j++) y[j] = so[(8*m+j)*9 + e];
        float r[8];
        #pragma unroll
        for(int ep=0;ep<8;ep++){
            float a = __ldg(&bias[ep]);
            #pragma unroll
            for(int j=0;j<8;j++) a = fmaf(y[j], __ldg(&W[ep*8+j]), a);
            r[ep]=a;
        }
        int i = e*512 + blockIdx.x*8 + m;
        float* op = &out[(b*NS + i)*8];
        *(float4*)op     = make_float4(r[0],r[1],r[2],r[3]);
        *(float4*)(op+4) = make_float4(r[4],r[5],r[6],r[7]);
    }
}

extern "C" void kernel_launch(void* const* d_in, const int* in_sizes, int n_in,
                              void* d_out, int out_size)
{
    const float* x     = (const float*)d_in[0];
    const float* theta = (const float*)d_in[1];
    const float* w     = (const float*)d_in[2];
    const float* bias  = (const float*)d_in[3];
    float* out = (float*)d_out;

    feat_kernel<<<NTOK/256, 256>>>(x, theta);
    dim3 g(NS/64, NB);
    attn_kernel<<<g, 128>>>(w, bias, out);
}

// round 12
// speedup vs baseline: 1.6527x; 1.6527x over previous
#include <cuda_runtime.h>

#define NB 16
#define NS 4096
#define NTOK (NB*NS)
#define CHUNK 256
#define VS 132             // padded u32 stride for V rows (bf16x2)
#define NCH (NS/CHUNK)
#define KFW (CHUNK/16*128) // K-frag words per chunk (2048)

// scratch (device globals: no allocation allowed)
__device__ float g_qrow[NTOK*8];            // tf32(q*log2e/sqrt2) [b][s][w] (Q operand)
__device__ unsigned int g_kfrag[NB*NS*8];   // tf32(q), mma-B-fragment order  (K operand)
__device__ unsigned short g_vhi[NB*8*NS];   // bf16(q)             [b][w][t]  (V operand)

typedef unsigned int u32;

__device__ __forceinline__ float ex2f(float x){float r; asm("ex2.approx.ftz.f32 %0,%1;":"=f"(r):"f"(x)); return r;}
__device__ __forceinline__ float tf32r(float x){u32 r; asm("cvt.rna.tf32.f32 %0,%1;":"=r"(r):"f"(x)); return __uint_as_float(r);}
// pack: result.lo = lo, result.hi = hi
__device__ __forceinline__ u32 pkbf(float hi, float lo){u32 r; asm("cvt.rn.bf16x2.f32 %0,%1,%2;":"=r"(r):"f"(hi),"f"(lo)); return r;}
__device__ __forceinline__ void cpa16(u32 dst, const void* src){
    asm volatile("cp.async.cg.shared.global [%0], [%1], 16;"::"r"(dst),"l"(src));
}
__device__ __forceinline__ void cpa_commit(){ asm volatile("cp.async.commit_group;"); }
__device__ __forceinline__ void cpa_wait1(){ asm volatile("cp.async.wait_group 1;"); }

__device__ __forceinline__ void mma_tf32(float* d, const u32* a, u32 b0, u32 b1){
    asm volatile("mma.sync.aligned.m16n8k8.row.col.f32.tf32.tf32.f32 "
        "{%0,%1,%2,%3},{%4,%5,%6,%7},{%8,%9},{%10,%11,%12,%13};"
        : "=f"(d[0]),"=f"(d[1]),"=f"(d[2]),"=f"(d[3])
        : "r"(a[0]),"r"(a[1]),"r"(a[2]),"r"(a[3]), "r"(b0),"r"(b1),
          "f"(0.f),"f"(0.f),"f"(0.f),"f"(0.f));
}
__device__ __forceinline__ void mma_bf16(float* d, const u32* a, u32 b0, u32 b1){
    asm volatile("mma.sync.aligned.m16n8k16.row.col.f32.bf16.bf16.f32 "
        "{%0,%1,%2,%3},{%4,%5,%6,%7},{%8,%9},{%0,%1,%2,%3};"
        : "+f"(d[0]),"+f"(d[1]),"+f"(d[2]),"+f"(d[3])
        : "r"(a[0]),"r"(a[1]),"r"(a[2]),"r"(a[3]), "r"(b0),"r"(b1));
}

// ---------------------------------------------------------------------------
// Kernel 1: quantum features (prefix cosine products).
//   Emits: Q (tf32, pre-scaled), K (tf32, mma-fragment order), V (bf16).
//   K fragment layout per 16-token block: lane(g,c)=g*4+c holds
//     {K[c][g], K[c+4][g], K[c][8+g], K[c+4][8+g]}  (one LDS.128 in attn)
// ---------------------------------------------------------------------------
__global__ void feat_kernel(const float* __restrict__ x, const float* __restrict__ theta)
{
    int tok = blockIdx.x*blockDim.x + threadIdx.x;
    float th[8];
    #pragma unroll
    for(int w=0;w<8;w++) th[w] = __ldg(&theta[w]);
    float4 x0 = *(const float4*)&x[tok*8];
    float4 x1 = *(const float4*)&x[tok*8+4];
    float c[8];
    c[0]=__cosf(x0.x+th[0]); c[1]=__cosf(x0.y+th[1]); c[2]=__cosf(x0.z+th[2]); c[3]=__cosf(x0.w+th[3]);
    c[4]=__cosf(x1.x+th[4]); c[5]=__cosf(x1.y+th[5]); c[6]=__cosf(x1.z+th[6]); c[7]=__cosf(x1.w+th[7]);
    float q[8];
    float p = c[0];
    #pragma unroll
    for(int w=1;w<8;w++){ p *= c[w]; q[w] = p; }
    float s = c[1];
    #pragma unroll
    for(int w=2;w<8;w++) s *= c[w];
    q[0] = s;                                   // CNOT-ring inverse image
    const float SC = 1.02013946f;               // log2(e)/sqrt(2)
    float qs[8];
    #pragma unroll
    for(int w=0;w<8;w++) qs[w]=tf32r(q[w]*SC);
    *(float4*)&g_qrow[tok*8]   = make_float4(qs[0],qs[1],qs[2],qs[3]);
    *(float4*)&g_qrow[tok*8+4] = make_float4(qs[4],qs[5],qs[6],qs[7]);
    int b = tok >> 12, t = tok & (NS-1);
    // K fragment-order scatter
    u32* kf = &g_kfrag[b*NS*8];
    int kbase = (t>>4)*128 + (t&7)*16 + ((t>>3)&1)*2;
    #pragma unroll
    for(int w=0;w<8;w++){
        float qv = q[w];
        kf[kbase + (w&3)*4 + (w>>2)] = __float_as_uint(tf32r(qv));
        g_vhi[(b*8+w)*NS + t] = (unsigned short)(pkbf(0.f, qv) & 0xffffu);
    }
}

// ---------------------------------------------------------------------------
// Kernel 2: flash attention via warp mma.sync + fused epilogue.
//   Two independent 16-t pipelines; K fragments via single LDS.128 each.
//   Per subtile: 1 LDS.128 + 2 tf32 mma -> S ; 8 ex2 ; 4 cvt ; 1 bf16 mma.
// ---------------------------------------------------------------------------
__global__ void __launch_bounds__(128, 8) attn_kernel(const float* __restrict__ W,
                                                      const float* __restrict__ bias,
                                                      float* __restrict__ out)
{
    __shared__ __align__(16) u32 skf[2][KFW];    // K fragments, 8KB/stage
    __shared__ __align__(16) u32 svh[2][8*VS];
    __shared__ float so[64*9];                   // o staging, stride 9

    const int b    = blockIdx.y;
    const int tid  = threadIdx.x;
    const int warp = tid >> 5, lane = tid & 31;
    const int g    = lane >> 2, c = lane & 3;
    const int row0 = blockIdx.x*64 + warp*16;

    // hoisted chunk-load addressing
    const int vr = tid >> 5, vo = tid & 31;
    const u32*            kfsrc = &g_kfrag[b*NS*8] + tid*4;      // +round*512
    const unsigned short* vsrc  = &g_vhi [b*8*NS + vr*NS] + vo*8;
    u32 skb  = (u32)__cvta_generic_to_shared(&skf[0][0]) + (u32)(tid*4)*4u;
    u32 svhb = (u32)__cvta_generic_to_shared(&svh[0][0]) + (u32)(vr*VS + vo*4)*4u;
    const u32 KSTG = KFW*4u, VSTG = 8*VS*4u;

    // Q fragment (held whole kernel)
    const float* qr = &g_qrow[(b*NS+row0)*8];
    u32 qa[4];
    qa[0] = __float_as_uint(qr[ g   *8 + c  ]);
    qa[1] = __float_as_uint(qr[(g+8)*8 + c  ]);
    qa[2] = __float_as_uint(qr[ g   *8 + c+4]);
    qa[3] = __float_as_uint(qr[(g+8)*8 + c+4]);

    float num0[4] = {0.f,0.f,0.f,0.f};
    float num1[4] = {0.f,0.f,0.f,0.f};
    float d0l=0.f, d0h=0.f, d1l=0.f, d1h=0.f;

    auto load_chunk = [&](int ch, int st){
        const u32*            ks = kfsrc + ch*(CHUNK*8);
        const unsigned short* vs = vsrc  + ch*CHUNK;
        u32 kb = skb  + (st ? KSTG : 0u);
        u32 hb = svhb + (st ? VSTG : 0u);
        #pragma unroll
        for(int k=0;k<4;k++) cpa16(kb + (u32)(k*512)*4u, ks + k*512);
        #pragma unroll
        for(int k=0;k<2;k++) cpa16(hb + (u32)(4*k*VS)*4u, vs + 4*k*NS);
        cpa_commit();
    };

    load_chunk(0, 0);

    for(int ch=0; ch<NCH; ch++){
        int st = ch & 1;
        if(ch+1 < NCH) load_chunk(ch+1, (ch+1)&1);
        else           cpa_commit();           // keep wait count uniform
        cpa_wait1();
        __syncthreads();

        const u32* KF = &skf[st][0];
        const u32* VH = &svh[st][0];

        #pragma unroll 2
        for(int pair=0; pair<CHUNK/32; pair++){
            const int tA = pair*32, tB = pair*32 + 16;
            uint4 fA = *(const uint4*)&KF[(pair*2  )*128 + lane*4];
            uint4 fB = *(const uint4*)&KF[(pair*2+1)*128 + lane*4];

            float Al[4], Ar[4], Bl[4], Br[4];
            mma_tf32(Al, qa, fA.x, fA.y);
            mma_tf32(Ar, qa, fA.z, fA.w);
            mma_tf32(Bl, qa, fB.x, fB.y);
            mma_tf32(Br, qa, fB.z, fB.w);

            Al[0]=ex2f(Al[0]); Al[1]=ex2f(Al[1]); Al[2]=ex2f(Al[2]); Al[3]=ex2f(Al[3]);
            Ar[0]=ex2f(Ar[0]); Ar[1]=ex2f(Ar[1]); Ar[2]=ex2f(Ar[2]); Ar[3]=ex2f(Ar[3]);
            Bl[0]=ex2f(Bl[0]); Bl[1]=ex2f(Bl[1]); Bl[2]=ex2f(Bl[2]); Bl[3]=ex2f(Bl[3]);
            Br[0]=ex2f(Br[0]); Br[1]=ex2f(Br[1]); Br[2]=ex2f(Br[2]); Br[3]=ex2f(Br[3]);

            d0l += Al[0]+Al[1]+Ar[0]+Ar[1];
            d0h += Al[2]+Al[3]+Ar[2]+Ar[3];
            d1l += Bl[0]+Bl[1]+Br[0]+Br[1];
            d1h += Bl[2]+Bl[3]+Br[2]+Br[3];

            u32 pA[4], pB[4];
            pA[0]=pkbf(Al[1],Al[0]); pA[1]=pkbf(Al[3],Al[2]);
            pA[2]=pkbf(Ar[1],Ar[0]); pA[3]=pkbf(Ar[3],Ar[2]);
            pB[0]=pkbf(Bl[1],Bl[0]); pB[1]=pkbf(Bl[3],Bl[2]);
            pB[2]=pkbf(Br[1],Br[0]); pB[3]=pkbf(Br[3],Br[2]);

            int viA = g*VS + (tA>>1);
            int viB = g*VS + (tB>>1);
            mma_bf16(num0, pA, VH[viA + c], VH[viA + 4 + c]);
            mma_bf16(num1, pB, VH[viB + c], VH[viB + 4 + c]);
        }
        __syncthreads();
    }

    float denl = d0l + d1l, denh = d0h + d1h;
    denl += __shfl_xor_sync(0xffffffffu, denl, 1);
    denl += __shfl_xor_sync(0xffffffffu, denl, 2);
    denh += __shfl_xor_sync(0xffffffffu, denh, 1);
    denh += __shfl_xor_sync(0xffffffffu, denh, 2);
    float invl = 1.0f/denl, invh = 1.0f/denh;

    // stage normalized o tile: so[localRow][e], stride 9
    int lr = warp*16 + g;
    so[ lr   *9 + 2*c] = (num0[0]+num1[0])*invl;  so[ lr   *9 + 2*c+1] = (num0[1]+num1[1])*invl;
    so[(lr+8)*9 + 2*c] = (num0[2]+num1[2])*invh;  so[(lr+8)*9 + 2*c+1] = (num0[3]+num1[3])*invh;
    __syncthreads();

    // fused epilogue: out[b, e*512 + 8*bx + m, :] = bias + so[8m+j][e] . W[:,j]
    if(tid < 64){
        int e = tid >> 3, m = tid & 7;
        float y[8];
        #pragma unroll
        for(int j=0;j<8;j++) y[j] = so[(8*m+j)*9 + e];
        float r[8];
        #pragma unroll
        for(int ep=0;ep<8;ep++){
            float a = __ldg(&bias[ep]);
            #pragma unroll
            for(int j=0;j<8;j++) a = fmaf(y[j], __ldg(&W[ep*8+j]), a);
            r[ep]=a;
        }
        int i = e*512 + blockIdx.x*8 + m;
        float* op = &out[(b*NS + i)*8];
        *(float4*)op     = make_float4(r[0],r[1],r[2],r[3]);
        *(float4*)(op+4) = make_float4(r[4],r[5],r[6],r[7]);
    }
}

extern "C" void kernel_launch(void* const* d_in, const int* in_sizes, int n_in,
                              void* d_out, int out_size)
{
    const float* x     = (const float*)d_in[0];
    const float* theta = (const float*)d_in[1];
    const float* w     = (const float*)d_in[2];
    const float* bias  = (const float*)d_in[3];
    float* out = (float*)d_out;

    feat_kernel<<<NTOK/256, 256>>>(x, theta);
    dim3 g(NS/64, NB);
    attn_kernel<<<g, 128>>>(w, bias, out);
}